// round 5
// baseline (speedup 1.0000x reference)
#include <cuda_runtime.h>
#include <cuda_fp16.h>
#include <math.h>

#define NN 100000
#define EE 1600000
#define KE 64
#define INC 128
#define HID 256
#define OC 16

typedef unsigned long long ull;

// ---- static device scratch ----
__device__ __half  g_Wh[(size_t)NN * KE];  // MLP_W^T fp16 [N,64]
__device__ float   g_S [(size_t)NN * KE];  // S fp32
__device__ __half  g_Sh[(size_t)NN * KE];  // S fp16 (SpMM2 gather)
__device__ int     g_deg[NN];
__device__ int     g_ptr[NN + 1];
__device__ int     g_pos[NN];
__device__ int     g_srt[EE];
__device__ int     g_bsum[128];
__device__ float   g_SS[KE * KE];
__device__ float   g_Wc[OC * INC];
__device__ float   g_bc[OC];
__device__ double  g_cut;
__device__ double  g_dt;
__device__ volatile unsigned g_bar;

// ---- packed f32x2 helpers (FFMA2: PTX-only on sm_103a) ----
__device__ __forceinline__ ull f2pack(float x, float y) {
    ull d; asm("mov.b64 %0, {%1, %2};" : "=l"(d) : "f"(x), "f"(y)); return d;
}
__device__ __forceinline__ void f2unpack(ull d, float& x, float& y) {
    asm("mov.b64 {%0, %1}, %2;" : "=f"(x), "=f"(y) : "l"(d));
}
__device__ __forceinline__ ull f2fma(ull a, ull b, ull c) {
    ull d; asm("fma.rn.f32x2 %0, %1, %2, %3;" : "=l"(d) : "l"(a), "l"(b), "l"(c)); return d;
}

// ---- software grid barrier: grid <= guaranteed-resident blocks ----
__device__ __forceinline__ void gsync(unsigned target) {
    __syncthreads();
    if (threadIdx.x == 0) {
        __threadfence();
        atomicAdd((unsigned*)&g_bar, 1u);
        while (g_bar < target) __nanosleep(64);
        __threadfence();
    }
    __syncthreads();
}

__global__ void __launch_bounds__(256, 6) k_persist(
    const float* __restrict__ W,        // MLP_W [64,N]
    const int*   __restrict__ row,
    const int*   __restrict__ col,
    const float* __restrict__ MLPb,
    const float* __restrict__ finW,
    const float* __restrict__ mlpxW,
    const float* __restrict__ mlpxb,
    const float* __restrict__ finb,
    const float* __restrict__ x,
    float*       __restrict__ out,
    int outIdx)
{
    const unsigned G = gridDim.x;
    const int bid = blockIdx.x;
    const int t   = threadIdx.x;
    const int tid = bid * 256 + t;
    const int stride = G * 256;

    __shared__ float  s_tile[32][33];
    __shared__ int    s_scan[256];
    __shared__ int    s_exc[128];
    __shared__ double s_red[8];
    __shared__ float4 s_rows[16][16];
    __shared__ float4 s_Wx[32][16];
    __shared__ float4 s_Wa[16][16];
    __shared__ float  s_bo[16];
    __shared__ double s_loss[256];
    __shared__ double s_dnrm;

    // ================= P0: hist + zero small =================
    if (bid == 0) {
        for (int i = t; i < KE * KE; i += 256) g_SS[i] = 0.f;
        if (t == 0) { g_cut = 0.0; g_dt = 0.0; }
    }
    for (int e = tid; e < EE; e += stride) atomicAdd(&g_deg[col[e]], 1);
    gsync(1u * G);

    // ================= P1: scan(98 blocks)  ||  transpose + wcomb (rest) =================
    if (bid < 98) {
        int c = bid;
        int base = c * 1024 + t * 4;
        int v0 = (base + 0 < NN) ? g_deg[base + 0] : 0;
        int v1 = (base + 1 < NN) ? g_deg[base + 1] : 0;
        int v2 = (base + 2 < NN) ? g_deg[base + 2] : 0;
        int v3 = (base + 3 < NN) ? g_deg[base + 3] : 0;
        int s = v0 + v1 + v2 + v3;
        s_scan[t] = s; __syncthreads();
        for (int off = 1; off < 256; off <<= 1) {
            int xv = (t >= off) ? s_scan[t - off] : 0;
            __syncthreads();
            s_scan[t] += xv;
            __syncthreads();
        }
        int run = s_scan[t] - s;
        if (t == 255) g_bsum[c] = s_scan[255];
        if (base + 0 < NN) g_ptr[base + 0] = run; run += v0;
        if (base + 1 < NN) g_ptr[base + 1] = run; run += v1;
        if (base + 2 < NN) g_ptr[base + 2] = run; run += v2;
        if (base + 3 < NN) g_ptr[base + 3] = run;
    } else {
        // wcomb (tiny) on the leading non-scan blocks
        for (int idx = (bid - 98) * 256 + t; idx < OC * INC + OC; idx += ((int)G - 98) * 256) {
            if (idx < OC * INC) {
                int o = idx >> 7, c = idx & 127;
                float s = 0.f;
                for (int h = 0; h < HID; h++) s += finW[o * 320 + h] * mlpxW[h * INC + c];
                g_Wc[idx] = s;
            } else {
                int o = idx - OC * INC;
                float s = finb[o];
                for (int h = 0; h < HID; h++) s += finW[o * 320 + h] * mlpxb[h];
                g_bc[o] = s;
            }
        }
        // transpose -> fp16
        for (int tb = bid - 98; tb < 6250; tb += (int)G - 98) {
            int v0 = (tb % 3125) * 32, k0 = (tb / 3125) * 32;
            int tx = t & 31, ty = t >> 5;
            __syncthreads();
            #pragma unroll
            for (int r = ty; r < 32; r += 8)
                s_tile[r][tx] = W[(size_t)(k0 + r) * NN + v0 + tx];
            __syncthreads();
            #pragma unroll
            for (int r = ty; r < 32; r += 8)
                g_Wh[(size_t)(v0 + r) * KE + k0 + tx] = __float2half(s_tile[tx][r]);
        }
    }
    gsync(2u * G);

    // ================= P2: redundant block-sum scan + apply offsets =================
    {
        int v = (t < 98) ? g_bsum[t] : 0;
        if (t < 128) s_scan[t] = v;
        __syncthreads();
        for (int off = 1; off < 128; off <<= 1) {
            int xv = 0;
            if (t < 128 && t >= off) xv = s_scan[t - off];
            __syncthreads();
            if (t < 128) s_scan[t] += xv;
            __syncthreads();
        }
        if (t < 128) s_exc[t] = s_scan[t] - v;
        __syncthreads();
        for (int i = tid; i < NN; i += stride) {
            int p = g_ptr[i] + s_exc[i >> 10];
            g_ptr[i] = p;
            g_pos[i] = p;
        }
        if (tid == 0) g_ptr[NN] = EE;
    }
    gsync(3u * G);

    // ================= P3: scatter edges into CSR =================
    for (int e = tid; e < EE; e += stride) {
        int p = atomicAdd(&g_pos[col[e]], 1);
        g_srt[p] = row[e];
    }
    gsync(4u * G);

    // ================= P4: SpMM1 + softmax + deg_term (warp/node) =================
    {
        int gw = tid >> 5, l = t & 31, wl = t >> 5;
        int nw = G * 8;
        const __half2* F = (const __half2*)g_Wh;
        float2 b2 = __ldg(&((const float2*)MLPb)[l]);
        double ddt = 0.0;
        for (int w = gw; w < NN; w += nw) {
            int s = g_ptr[w], e = g_ptr[w + 1];
            float a0 = 0.f, a1 = 0.f;
            int i = s;
            for (; i + 4 <= e; i += 4) {
                int s0 = __ldg(&g_srt[i]),     s1 = __ldg(&g_srt[i + 1]);
                int s2 = __ldg(&g_srt[i + 2]), s3 = __ldg(&g_srt[i + 3]);
                float2 f0 = __half22float2(__ldg(&F[(size_t)s0 * 32 + l]));
                float2 f1 = __half22float2(__ldg(&F[(size_t)s1 * 32 + l]));
                float2 f2 = __half22float2(__ldg(&F[(size_t)s2 * 32 + l]));
                float2 f3 = __half22float2(__ldg(&F[(size_t)s3 * 32 + l]));
                a0 += (f0.x + f1.x) + (f2.x + f3.x);
                a1 += (f0.y + f1.y) + (f2.y + f3.y);
            }
            for (; i < e; i++) {
                int s0 = __ldg(&g_srt[i]);
                float2 f = __half22float2(__ldg(&F[(size_t)s0 * 32 + l]));
                a0 += f.x; a1 += f.y;
            }
            a0 += b2.x; a1 += b2.y;
            float m = fmaxf(a0, a1);
            #pragma unroll
            for (int d = 16; d >= 1; d >>= 1) m = fmaxf(m, __shfl_xor_sync(0xffffffffu, m, d));
            float e0 = expf(a0 - m), e1 = expf(a1 - m);
            float sum = e0 + e1;
            #pragma unroll
            for (int d = 16; d >= 1; d >>= 1) sum += __shfl_xor_sync(0xffffffffu, sum, d);
            float inv = 1.f / sum;
            float s0 = e0 * inv, s1 = e1 * inv;
            ((float2*)g_S)[(size_t)w * 32 + l] = make_float2(s0, s1);
            ((__half2*)g_Sh)[(size_t)w * 32 + l] = __floats2half2_rn(s0, s1);
            float ssq = s0 * s0 + s1 * s1;
            #pragma unroll
            for (int d = 16; d >= 1; d >>= 1) ssq += __shfl_xor_sync(0xffffffffu, ssq, d);
            if (l == 0) ddt += (double)(e - s) * (double)ssq;
        }
        __syncthreads();
        if (l == 0) s_red[wl] = ddt;
        __syncthreads();
        if (t == 0) {
            double a = 0.0;
            #pragma unroll
            for (int q = 0; q < 8; q++) a += s_red[q];
            atomicAdd(&g_dt, a);
        }
    }
    gsync(5u * G);

    // ================= P5: SpMM2 + cut (warp/node) =================
    {
        int gw = tid >> 5, l = t & 31, wl = t >> 5;
        int nw = G * 8;
        const __half2* F = (const __half2*)g_Sh;
        double dcut = 0.0;
        for (int w = gw; w < NN; w += nw) {
            int s = g_ptr[w], e = g_ptr[w + 1];
            float a0 = 0.f, a1 = 0.f;
            int i = s;
            for (; i + 4 <= e; i += 4) {
                int s0 = __ldg(&g_srt[i]),     s1 = __ldg(&g_srt[i + 1]);
                int s2 = __ldg(&g_srt[i + 2]), s3 = __ldg(&g_srt[i + 3]);
                float2 f0 = __half22float2(__ldg(&F[(size_t)s0 * 32 + l]));
                float2 f1 = __half22float2(__ldg(&F[(size_t)s1 * 32 + l]));
                float2 f2 = __half22float2(__ldg(&F[(size_t)s2 * 32 + l]));
                float2 f3 = __half22float2(__ldg(&F[(size_t)s3 * 32 + l]));
                a0 += (f0.x + f1.x) + (f2.x + f3.x);
                a1 += (f0.y + f1.y) + (f2.y + f3.y);
            }
            for (; i < e; i++) {
                int s0 = __ldg(&g_srt[i]);
                float2 f = __half22float2(__ldg(&F[(size_t)s0 * 32 + l]));
                a0 += f.x; a1 += f.y;
            }
            float2 sc = ((const float2*)g_S)[(size_t)w * 32 + l];
            float dot = a0 * sc.x + a1 * sc.y;
            #pragma unroll
            for (int d = 16; d >= 1; d >>= 1) dot += __shfl_xor_sync(0xffffffffu, dot, d);
            if (l == 0) dcut += (double)dot;
        }
        __syncthreads();
        if (l == 0) s_red[wl] = dcut;
        __syncthreads();
        if (t == 0) {
            double a = 0.0;
            #pragma unroll
            for (int q = 0; q < 8; q++) a += s_red[q];
            atomicAdd(&g_cut, a);
        }
    }
    gsync(6u * G);

    // ================= P6: SSmat (bid < ssp)  ||  final (rest), FFMA2 =================
    {
        int ssp = (int)((G * 4u) / 7u);           // ~57%: balance 410M vs 307M MACs
        if (bid < ssp) {
            int ti = t >> 4, tj = t & 15;
            ull acc2[4][2];
            #pragma unroll
            for (int p = 0; p < 4; p++) { acc2[p][0] = 0ull; acc2[p][1] = 0ull; }
            const float4* S4 = (const float4*)g_S;
            for (int rb = bid * 16; rb < NN; rb += ssp * 16) {
                __syncthreads();
                s_rows[t >> 4][t & 15] = S4[(size_t)(rb + (t >> 4)) * 16 + (t & 15)];
                __syncthreads();
                #pragma unroll 4
                for (int r = 0; r < 16; r++) {
                    float4 a = s_rows[r][ti];
                    ulonglong2 b = *(const ulonglong2*)&s_rows[r][tj];
                    ull a0 = f2pack(a.x, a.x), a1 = f2pack(a.y, a.y);
                    ull a2 = f2pack(a.z, a.z), a3 = f2pack(a.w, a.w);
                    acc2[0][0] = f2fma(a0, b.x, acc2[0][0]); acc2[0][1] = f2fma(a0, b.y, acc2[0][1]);
                    acc2[1][0] = f2fma(a1, b.x, acc2[1][0]); acc2[1][1] = f2fma(a1, b.y, acc2[1][1]);
                    acc2[2][0] = f2fma(a2, b.x, acc2[2][0]); acc2[2][1] = f2fma(a2, b.y, acc2[2][1]);
                    acc2[3][0] = f2fma(a3, b.x, acc2[3][0]); acc2[3][1] = f2fma(a3, b.y, acc2[3][1]);
                }
            }
            #pragma unroll
            for (int p = 0; p < 4; p++) {
                float v0, v1, v2, v3;
                f2unpack(acc2[p][0], v0, v1);
                f2unpack(acc2[p][1], v2, v3);
                int base = (ti * 4 + p) * KE + tj * 4;
                atomicAdd(&g_SS[base + 0], v0);
                atomicAdd(&g_SS[base + 1], v1);
                atomicAdd(&g_SS[base + 2], v2);
                atomicAdd(&g_SS[base + 3], v3);
            }
        } else {
            for (int idx = t; idx < 512; idx += 256) {
                int c4 = idx >> 4, o = idx & 15;
                s_Wx[c4][o] = ((const float4*)g_Wc)[o * 32 + c4];
            }
            {
                int k4 = t >> 4, o = t & 15;
                s_Wa[k4][o] = ((const float4*)finW)[o * 80 + 64 + k4];
            }
            if (t < 16) s_bo[t] = g_bc[t];
            __syncthreads();
            int slot = t >> 4, o = t & 15;
            const ulonglong2* x2 = (const ulonglong2*)x;
            const ulonglong2* S2 = (const ulonglong2*)g_S;
            for (int g = bid - ssp; g < 1563; g += (int)G - ssp) {
                int n0 = g * 64 + slot * 4;
                ull acc[4];
                #pragma unroll
                for (int j = 0; j < 4; j++) acc[j] = f2pack(s_bo[o], 0.f);
                #pragma unroll 4
                for (int c4 = 0; c4 < 32; c4++) {
                    ulonglong2 wv = *(const ulonglong2*)&s_Wx[c4][o];
                    #pragma unroll
                    for (int j = 0; j < 4; j++) {
                        int n = n0 + j; if (n >= NN) n = NN - 1;
                        ulonglong2 xv = x2[(size_t)n * 32 + c4];
                        acc[j] = f2fma(xv.x, wv.x, acc[j]);
                        acc[j] = f2fma(xv.y, wv.y, acc[j]);
                    }
                }
                #pragma unroll 4
                for (int k4 = 0; k4 < 16; k4++) {
                    ulonglong2 wv = *(const ulonglong2*)&s_Wa[k4][o];
                    #pragma unroll
                    for (int j = 0; j < 4; j++) {
                        int n = n0 + j; if (n >= NN) n = NN - 1;
                        ulonglong2 sv = S2[(size_t)n * 16 + k4];
                        acc[j] = f2fma(sv.x, wv.x, acc[j]);
                        acc[j] = f2fma(sv.y, wv.y, acc[j]);
                    }
                }
                #pragma unroll
                for (int j = 0; j < 4; j++) {
                    float lo, hi;
                    f2unpack(acc[j], lo, hi);
                    float a = lo + hi;
                    float m = a;
                    #pragma unroll
                    for (int d = 1; d < 16; d <<= 1) m = fmaxf(m, __shfl_xor_sync(0xffffffffu, m, d));
                    float ex = expf(a - m);
                    float sum = ex;
                    #pragma unroll
                    for (int d = 1; d < 16; d <<= 1) sum += __shfl_xor_sync(0xffffffffu, sum, d);
                    int n = n0 + j;
                    if (n < NN) out[(size_t)n * 16 + o] = a - m - logf(sum);
                }
            }
        }
    }
    gsync(7u * G);

    // ================= P7: loss (block 0) =================
    if (bid == 0) {
        double s = 0.0;
        for (int i = t; i < KE * KE; i += 256) { double v = (double)g_SS[i]; s += v * v; }
        s_loss[t] = s; __syncthreads();
        for (int off = 128; off >= 1; off >>= 1) { if (t < off) s_loss[t] += s_loss[t + off]; __syncthreads(); }
        if (t == 0) s_dnrm = sqrt(s_loss[0]);
        __syncthreads();
        double s2 = 0.0;
        for (int i = t; i < KE * KE; i += 256) {
            double v = (double)g_SS[i] / s_dnrm;
            if ((i >> 6) == (i & 63)) v -= 0.125;   // I / sqrt(64)
            s2 += v * v;
        }
        s_loss[t] = s2; __syncthreads();
        for (int off = 128; off >= 1; off >>= 1) { if (t < off) s_loss[t] += s_loss[t + off]; __syncthreads(); }
        if (t == 0) {
            double loss = -(g_cut / g_dt) + sqrt(s_loss[0]);
            out[outIdx] = (float)loss;
        }
    }
}

// ================================================================ launch
extern "C" void kernel_launch(void* const* d_in, const int* in_sizes, int n_in,
                              void* d_out, int out_size) {
    const float* x     = (const float*)d_in[0];
    const int*   ei    = (const int*)  d_in[1];
    const float* MLPW  = (const float*)d_in[2];
    const float* MLPb  = (const float*)d_in[3];
    const float* mlpxW = (const float*)d_in[4];
    const float* mlpxb = (const float*)d_in[5];
    const float* finW  = (const float*)d_in[6];
    const float* finb  = (const float*)d_in[7];
    float* out = (float*)d_out;

    const int* row = ei;
    const int* col = ei + EE;

    int nb = 0;
    cudaOccupancyMaxActiveBlocksPerMultiprocessor(&nb, k_persist, 256, 0);
    if (nb <= 0) nb = 1;
    int smc = 0;
    cudaDeviceGetAttribute(&smc, cudaDevAttrMultiProcessorCount, 0);
    if (smc <= 0) smc = 148;
    unsigned G = (unsigned)(nb * smc);
    if (G > 2048u) G = 2048u;

    void* degp = nullptr;  cudaGetSymbolAddress(&degp, g_deg);
    void* barp = nullptr;  cudaGetSymbolAddress(&barp, g_bar);
    cudaMemsetAsync(degp, 0, NN * sizeof(int));
    cudaMemsetAsync(barp, 0, sizeof(unsigned));

    k_persist<<<G, 256>>>(MLPW, row, col, MLPb, finW, mlpxW, mlpxb, finb, x, out,
                          out_size - 1);
}

// round 6
// speedup vs baseline: 1.0240x; 1.0240x over previous
#include <cuda_runtime.h>
#include <cuda_fp16.h>
#include <math.h>

#define NN 100000
#define EE 1600000
#define KE 64
#define INC 128
#define HID 256
#define OC 16

typedef unsigned long long ull;

// ---- static device scratch ----
__device__ __half  g_Wh[(size_t)NN * KE];  // MLP_W^T fp16 [N,64]
__device__ float   g_S [(size_t)NN * KE];  // S fp32
__device__ __half  g_Sh[(size_t)NN * KE];  // S fp16 (SpMM2 gather)
__device__ int     g_deg[NN];
__device__ int     g_ptr[NN + 1];
__device__ int     g_pos[NN];
__device__ int     g_srt[EE];
__device__ int     g_bsum[128];
__device__ float   g_SS[KE * KE];
__device__ float   g_Wc[OC * INC];
__device__ float   g_bc[OC];
__device__ double  g_cut;
__device__ double  g_dt;
__device__ volatile unsigned g_bar;

// ---- packed f32x2 helpers ----
__device__ __forceinline__ ull f2pack(float x, float y) {
    ull d; asm("mov.b64 %0, {%1, %2};" : "=l"(d) : "f"(x), "f"(y)); return d;
}
__device__ __forceinline__ void f2unpack(ull d, float& x, float& y) {
    asm("mov.b64 {%0, %1}, %2;" : "=f"(x), "=f"(y) : "l"(d));
}
__device__ __forceinline__ ull f2fma(ull a, ull b, ull c) {
    ull d; asm("fma.rn.f32x2 %0, %1, %2, %3;" : "=l"(d) : "l"(a), "l"(b), "l"(c)); return d;
}

// ---- software grid barrier: grid <= guaranteed-resident blocks ----
__device__ __forceinline__ void gsync(unsigned target) {
    __syncthreads();
    if (threadIdx.x == 0) {
        __threadfence();
        atomicAdd((unsigned*)&g_bar, 1u);
        while (g_bar < target) __nanosleep(64);
        __threadfence();
    }
    __syncthreads();
}

__global__ void __launch_bounds__(256) k_persist(
    const float* __restrict__ W,        // MLP_W [64,N]
    const int*   __restrict__ row,
    const int*   __restrict__ col,
    const float* __restrict__ MLPb,
    const float* __restrict__ finW,
    const float* __restrict__ mlpxW,
    const float* __restrict__ mlpxb,
    const float* __restrict__ finb,
    const float* __restrict__ x,
    float*       __restrict__ out,
    int outIdx)
{
    const unsigned G = gridDim.x;
    const int bid = blockIdx.x;
    const int t   = threadIdx.x;
    const int tid = bid * 256 + t;
    const int stride = G * 256;

    __shared__ float  s_tile[32][33];
    __shared__ int    s_scan[256];
    __shared__ int    s_exc[128];
    __shared__ double s_red[8];
    __shared__ float4 s_rows[16][16];
    __shared__ float4 s_Wx[32][16];
    __shared__ float4 s_Wa[16][16];
    __shared__ float  s_bo[16];
    __shared__ double s_loss[256];
    __shared__ double s_dnrm;

    // ================= P0: hist (int4) + zero small =================
    if (bid == 0) {
        for (int i = t; i < KE * KE; i += 256) g_SS[i] = 0.f;
        if (t == 0) { g_cut = 0.0; g_dt = 0.0; }
    }
    {
        const int4* c4 = (const int4*)col;
        for (int e = tid; e < EE / 4; e += stride) {
            int4 c = __ldg(&c4[e]);
            atomicAdd(&g_deg[c.x], 1);
            atomicAdd(&g_deg[c.y], 1);
            atomicAdd(&g_deg[c.z], 1);
            atomicAdd(&g_deg[c.w], 1);
        }
    }
    gsync(1u * G);

    // ================= P1: scan(98 blocks)  ||  transpose + wcomb (rest) =================
    if (bid < 98) {
        int c = bid;
        int base = c * 1024 + t * 4;
        int v0 = (base + 0 < NN) ? g_deg[base + 0] : 0;
        int v1 = (base + 1 < NN) ? g_deg[base + 1] : 0;
        int v2 = (base + 2 < NN) ? g_deg[base + 2] : 0;
        int v3 = (base + 3 < NN) ? g_deg[base + 3] : 0;
        int s = v0 + v1 + v2 + v3;
        s_scan[t] = s; __syncthreads();
        for (int off = 1; off < 256; off <<= 1) {
            int xv = (t >= off) ? s_scan[t - off] : 0;
            __syncthreads();
            s_scan[t] += xv;
            __syncthreads();
        }
        int run = s_scan[t] - s;
        if (t == 255) g_bsum[c] = s_scan[255];
        if (base + 0 < NN) g_ptr[base + 0] = run; run += v0;
        if (base + 1 < NN) g_ptr[base + 1] = run; run += v1;
        if (base + 2 < NN) g_ptr[base + 2] = run; run += v2;
        if (base + 3 < NN) g_ptr[base + 3] = run;
    } else {
        for (int idx = (bid - 98) * 256 + t; idx < OC * INC + OC; idx += ((int)G - 98) * 256) {
            if (idx < OC * INC) {
                int o = idx >> 7, c = idx & 127;
                float s = 0.f;
                for (int h = 0; h < HID; h++) s += finW[o * 320 + h] * mlpxW[h * INC + c];
                g_Wc[idx] = s;
            } else {
                int o = idx - OC * INC;
                float s = finb[o];
                for (int h = 0; h < HID; h++) s += finW[o * 320 + h] * mlpxb[h];
                g_bc[o] = s;
            }
        }
        for (int tb = bid - 98; tb < 6250; tb += (int)G - 98) {
            int v0 = (tb % 3125) * 32, k0 = (tb / 3125) * 32;
            int tx = t & 31, ty = t >> 5;
            __syncthreads();
            #pragma unroll
            for (int r = ty; r < 32; r += 8)
                s_tile[r][tx] = W[(size_t)(k0 + r) * NN + v0 + tx];
            __syncthreads();
            #pragma unroll
            for (int r = ty; r < 32; r += 8)
                g_Wh[(size_t)(v0 + r) * KE + k0 + tx] = __float2half(s_tile[tx][r]);
        }
    }
    gsync(2u * G);

    // ================= P2: redundant block-sum scan + apply offsets =================
    {
        int v = (t < 98) ? g_bsum[t] : 0;
        if (t < 128) s_scan[t] = v;
        __syncthreads();
        for (int off = 1; off < 128; off <<= 1) {
            int xv = 0;
            if (t < 128 && t >= off) xv = s_scan[t - off];
            __syncthreads();
            if (t < 128) s_scan[t] += xv;
            __syncthreads();
        }
        if (t < 128) s_exc[t] = s_scan[t] - v;
        __syncthreads();
        for (int i = tid; i < NN; i += stride) {
            int p = g_ptr[i] + s_exc[i >> 10];
            g_ptr[i] = p;
            g_pos[i] = p;
        }
        if (tid == 0) g_ptr[NN] = EE;
    }
    gsync(3u * G);

    // ================= P3: scatter edges into CSR (int4 loads) =================
    {
        const int4* c4 = (const int4*)col;
        const int4* r4 = (const int4*)row;
        for (int e = tid; e < EE / 4; e += stride) {
            int4 c = __ldg(&c4[e]);
            int4 r = __ldg(&r4[e]);
            int p0 = atomicAdd(&g_pos[c.x], 1); g_srt[p0] = r.x;
            int p1 = atomicAdd(&g_pos[c.y], 1); g_srt[p1] = r.y;
            int p2 = atomicAdd(&g_pos[c.z], 1); g_srt[p2] = r.z;
            int p3 = atomicAdd(&g_pos[c.w], 1); g_srt[p3] = r.w;
        }
    }
    gsync(4u * G);

    // ================= P4: SpMM1 + softmax + deg_term (warp/node) =================
    {
        int gw = tid >> 5, l = t & 31, wl = t >> 5;
        int nw = G * 8;
        const __half2* F = (const __half2*)g_Wh;
        float2 b2 = __ldg(&((const float2*)MLPb)[l]);
        double ddt = 0.0;
        for (int w = gw; w < NN; w += nw) {
            int s = g_ptr[w], e = g_ptr[w + 1];
            float a0 = 0.f, a1 = 0.f;
            int i = s;
            for (; i + 4 <= e; i += 4) {
                int s0 = __ldg(&g_srt[i]),     s1 = __ldg(&g_srt[i + 1]);
                int s2 = __ldg(&g_srt[i + 2]), s3 = __ldg(&g_srt[i + 3]);
                float2 f0 = __half22float2(__ldg(&F[(size_t)s0 * 32 + l]));
                float2 f1 = __half22float2(__ldg(&F[(size_t)s1 * 32 + l]));
                float2 f2 = __half22float2(__ldg(&F[(size_t)s2 * 32 + l]));
                float2 f3 = __half22float2(__ldg(&F[(size_t)s3 * 32 + l]));
                a0 += (f0.x + f1.x) + (f2.x + f3.x);
                a1 += (f0.y + f1.y) + (f2.y + f3.y);
            }
            for (; i < e; i++) {
                int s0 = __ldg(&g_srt[i]);
                float2 f = __half22float2(__ldg(&F[(size_t)s0 * 32 + l]));
                a0 += f.x; a1 += f.y;
            }
            a0 += b2.x; a1 += b2.y;
            float m = fmaxf(a0, a1);
            #pragma unroll
            for (int d = 16; d >= 1; d >>= 1) m = fmaxf(m, __shfl_xor_sync(0xffffffffu, m, d));
            float e0 = expf(a0 - m), e1 = expf(a1 - m);
            float sum = e0 + e1;
            #pragma unroll
            for (int d = 16; d >= 1; d >>= 1) sum += __shfl_xor_sync(0xffffffffu, sum, d);
            float inv = 1.f / sum;
            float s0 = e0 * inv, s1 = e1 * inv;
            ((float2*)g_S)[(size_t)w * 32 + l] = make_float2(s0, s1);
            ((__half2*)g_Sh)[(size_t)w * 32 + l] = __floats2half2_rn(s0, s1);
            float ssq = s0 * s0 + s1 * s1;
            #pragma unroll
            for (int d = 16; d >= 1; d >>= 1) ssq += __shfl_xor_sync(0xffffffffu, ssq, d);
            if (l == 0) ddt += (double)(e - s) * (double)ssq;
        }
        __syncthreads();
        if (l == 0) s_red[wl] = ddt;
        __syncthreads();
        if (t == 0) {
            double a = 0.0;
            #pragma unroll
            for (int q = 0; q < 8; q++) a += s_red[q];
            atomicAdd(&g_dt, a);
        }
    }
    gsync(5u * G);

    // ================= P5: SpMM2 + cut (warp/node) =================
    {
        int gw = tid >> 5, l = t & 31, wl = t >> 5;
        int nw = G * 8;
        const __half2* F = (const __half2*)g_Sh;
        double dcut = 0.0;
        for (int w = gw; w < NN; w += nw) {
            int s = g_ptr[w], e = g_ptr[w + 1];
            float a0 = 0.f, a1 = 0.f;
            int i = s;
            for (; i + 4 <= e; i += 4) {
                int s0 = __ldg(&g_srt[i]),     s1 = __ldg(&g_srt[i + 1]);
                int s2 = __ldg(&g_srt[i + 2]), s3 = __ldg(&g_srt[i + 3]);
                float2 f0 = __half22float2(__ldg(&F[(size_t)s0 * 32 + l]));
                float2 f1 = __half22float2(__ldg(&F[(size_t)s1 * 32 + l]));
                float2 f2 = __half22float2(__ldg(&F[(size_t)s2 * 32 + l]));
                float2 f3 = __half22float2(__ldg(&F[(size_t)s3 * 32 + l]));
                a0 += (f0.x + f1.x) + (f2.x + f3.x);
                a1 += (f0.y + f1.y) + (f2.y + f3.y);
            }
            for (; i < e; i++) {
                int s0 = __ldg(&g_srt[i]);
                float2 f = __half22float2(__ldg(&F[(size_t)s0 * 32 + l]));
                a0 += f.x; a1 += f.y;
            }
            float2 sc = ((const float2*)g_S)[(size_t)w * 32 + l];
            float dot = a0 * sc.x + a1 * sc.y;
            #pragma unroll
            for (int d = 16; d >= 1; d >>= 1) dot += __shfl_xor_sync(0xffffffffu, dot, d);
            if (l == 0) dcut += (double)dot;
        }
        __syncthreads();
        if (l == 0) s_red[wl] = dcut;
        __syncthreads();
        if (t == 0) {
            double a = 0.0;
            #pragma unroll
            for (int q = 0; q < 8; q++) a += s_red[q];
            atomicAdd(&g_cut, a);
        }
    }
    gsync(6u * G);

    // ================= P6: SSmat FFMA2 (bid < ssp)  ||  final float4 (rest) =================
    {
        int ssp = (int)((G * 4u) / 7u);
        if (bid < ssp) {
            int ti = t >> 4, tj = t & 15;
            ull acc2[4][2];
            #pragma unroll
            for (int p = 0; p < 4; p++) { acc2[p][0] = 0ull; acc2[p][1] = 0ull; }
            const float4* S4 = (const float4*)g_S;
            for (int rb = bid * 16; rb < NN; rb += ssp * 16) {
                __syncthreads();
                s_rows[t >> 4][t & 15] = S4[(size_t)(rb + (t >> 4)) * 16 + (t & 15)];
                __syncthreads();
                #pragma unroll 4
                for (int r = 0; r < 16; r++) {
                    float4 a = s_rows[r][ti];
                    ulonglong2 b = *(const ulonglong2*)&s_rows[r][tj];
                    ull a0 = f2pack(a.x, a.x), a1 = f2pack(a.y, a.y);
                    ull a2 = f2pack(a.z, a.z), a3 = f2pack(a.w, a.w);
                    acc2[0][0] = f2fma(a0, b.x, acc2[0][0]); acc2[0][1] = f2fma(a0, b.y, acc2[0][1]);
                    acc2[1][0] = f2fma(a1, b.x, acc2[1][0]); acc2[1][1] = f2fma(a1, b.y, acc2[1][1]);
                    acc2[2][0] = f2fma(a2, b.x, acc2[2][0]); acc2[2][1] = f2fma(a2, b.y, acc2[2][1]);
                    acc2[3][0] = f2fma(a3, b.x, acc2[3][0]); acc2[3][1] = f2fma(a3, b.y, acc2[3][1]);
                }
            }
            #pragma unroll
            for (int p = 0; p < 4; p++) {
                float v0, v1, v2, v3;
                f2unpack(acc2[p][0], v0, v1);
                f2unpack(acc2[p][1], v2, v3);
                int base = (ti * 4 + p) * KE + tj * 4;
                atomicAdd(&g_SS[base + 0], v0);
                atomicAdd(&g_SS[base + 1], v1);
                atomicAdd(&g_SS[base + 2], v2);
                atomicAdd(&g_SS[base + 3], v3);
            }
        } else {
            for (int idx = t; idx < 512; idx += 256) {
                int c4 = idx >> 4, o = idx & 15;
                s_Wx[c4][o] = ((const float4*)g_Wc)[o * 32 + c4];
            }
            {
                int k4 = t >> 4, o = t & 15;
                s_Wa[k4][o] = ((const float4*)finW)[o * 80 + 64 + k4];
            }
            if (t < 16) s_bo[t] = g_bc[t];
            __syncthreads();
            const float4* x4 = (const float4*)x;
            const float4* S4 = (const float4*)g_S;
            for (int g = bid - ssp; g < 6250; g += (int)G - ssp) {
                int n = g * 16 + (t >> 4);
                int o = t & 15;
                float acc = s_bo[o];
                #pragma unroll 8
                for (int c4 = 0; c4 < 32; c4++) {
                    float4 xv = x4[(size_t)n * 32 + c4];
                    float4 wv = s_Wx[c4][o];
                    acc += xv.x * wv.x + xv.y * wv.y + xv.z * wv.z + xv.w * wv.w;
                }
                #pragma unroll 8
                for (int k4 = 0; k4 < 16; k4++) {
                    float4 sv = S4[(size_t)n * 16 + k4];
                    float4 wv = s_Wa[k4][o];
                    acc += sv.x * wv.x + sv.y * wv.y + sv.z * wv.z + sv.w * wv.w;
                }
                float m = acc;
                #pragma unroll
                for (int d = 1; d < 16; d <<= 1) m = fmaxf(m, __shfl_xor_sync(0xffffffffu, m, d));
                float ex = expf(acc - m);
                float sum = ex;
                #pragma unroll
                for (int d = 1; d < 16; d <<= 1) sum += __shfl_xor_sync(0xffffffffu, sum, d);
                out[(size_t)n * 16 + o] = acc - m - logf(sum);
            }
        }
    }
    gsync(7u * G);

    // ================= P7: loss (block 0) =================
    if (bid == 0) {
        double s = 0.0;
        for (int i = t; i < KE * KE; i += 256) { double v = (double)g_SS[i]; s += v * v; }
        s_loss[t] = s; __syncthreads();
        for (int off = 128; off >= 1; off >>= 1) { if (t < off) s_loss[t] += s_loss[t + off]; __syncthreads(); }
        if (t == 0) s_dnrm = sqrt(s_loss[0]);
        __syncthreads();
        double s2 = 0.0;
        for (int i = t; i < KE * KE; i += 256) {
            double v = (double)g_SS[i] / s_dnrm;
            if ((i >> 6) == (i & 63)) v -= 0.125;   // I / sqrt(64)
            s2 += v * v;
        }
        s_loss[t] = s2; __syncthreads();
        for (int off = 128; off >= 1; off >>= 1) { if (t < off) s_loss[t] += s_loss[t + off]; __syncthreads(); }
        if (t == 0) {
            double loss = -(g_cut / g_dt) + sqrt(s_loss[0]);
            out[outIdx] = (float)loss;
        }
    }
}

// ================================================================ launch
extern "C" void kernel_launch(void* const* d_in, const int* in_sizes, int n_in,
                              void* d_out, int out_size) {
    const float* x     = (const float*)d_in[0];
    const int*   ei    = (const int*)  d_in[1];
    const float* MLPW  = (const float*)d_in[2];
    const float* MLPb  = (const float*)d_in[3];
    const float* mlpxW = (const float*)d_in[4];
    const float* mlpxb = (const float*)d_in[5];
    const float* finW  = (const float*)d_in[6];
    const float* finb  = (const float*)d_in[7];
    float* out = (float*)d_out;

    const int* row = ei;
    const int* col = ei + EE;

    int nb = 0;
    cudaOccupancyMaxActiveBlocksPerMultiprocessor(&nb, k_persist, 256, 0);
    if (nb <= 0) nb = 1;
    int smc = 0;
    cudaDeviceGetAttribute(&smc, cudaDevAttrMultiProcessorCount, 0);
    if (smc <= 0) smc = 148;
    unsigned G = (unsigned)(nb * smc);
    if (G > 2048u) G = 2048u;

    void* degp = nullptr;  cudaGetSymbolAddress(&degp, g_deg);
    void* barp = nullptr;  cudaGetSymbolAddress(&barp, g_bar);
    cudaMemsetAsync(degp, 0, NN * sizeof(int));
    cudaMemsetAsync(barp, 0, sizeof(unsigned));

    k_persist<<<G, 256>>>(MLPW, row, col, MLPb, finW, mlpxW, mlpxb, finb, x, out,
                          out_size - 1);
}

// round 7
// speedup vs baseline: 1.1814x; 1.1537x over previous
#include <cuda_runtime.h>
#include <cuda_fp16.h>
#include <math.h>

#define NN 100000
#define EE 1600000
#define KE 64
#define INC 128
#define HID 256
#define OC 16

typedef unsigned long long ull;

// ---- static device scratch ----
__device__ __half  g_Wh[(size_t)NN * KE];  // MLP_W^T fp16 [N,64]
__device__ float   g_S [(size_t)NN * KE];  // S fp32
__device__ __half  g_Sh[(size_t)NN * KE];  // S fp16 (SpMM2 gather)
__device__ int     g_deg[NN];
__device__ int     g_ptr[NN + 1];
__device__ int     g_pos[NN];
__device__ int     g_srt[EE];
__device__ int     g_bsum[128];
__device__ float   g_SS[KE * KE];
__device__ float   g_Wc[OC * INC];
__device__ float   g_bc[OC];
__device__ double  g_cut;
__device__ double  g_dt;
__device__ volatile unsigned g_bar;

// ---- software grid barrier: grid <= guaranteed-resident blocks ----
__device__ __forceinline__ void gsync(unsigned target) {
    __syncthreads();
    if (threadIdx.x == 0) {
        __threadfence();
        atomicAdd((unsigned*)&g_bar, 1u);
        while (g_bar < target) __nanosleep(64);
        __threadfence();
    }
    __syncthreads();
}

__global__ void __launch_bounds__(256) k_persist(
    const float* __restrict__ W,        // MLP_W [64,N]
    const int*   __restrict__ row,
    const int*   __restrict__ col,
    const float* __restrict__ MLPb,
    const float* __restrict__ finW,
    const float* __restrict__ mlpxW,
    const float* __restrict__ mlpxb,
    const float* __restrict__ finb,
    const float* __restrict__ x,
    float*       __restrict__ out,
    int outIdx)
{
    const unsigned G = gridDim.x;
    const int bid = blockIdx.x;
    const int t   = threadIdx.x;
    const int tid = bid * 256 + t;
    const int stride = G * 256;

    __shared__ float  s_tile[32][33];
    __shared__ int    s_scan[256];
    __shared__ int    s_exc[128];
    __shared__ double s_red[16];
    __shared__ float4 s_rows[16][16];
    __shared__ float4 s_Wx[32][16];
    __shared__ float4 s_Wa[16][16];
    __shared__ float  s_bo[16];
    __shared__ double s_loss[256];
    __shared__ double s_dnrm;

    // ================= P0: hist | transpose->fp16 | wcomb | zero small =================
    if (bid == 0) {
        for (int i = t; i < KE * KE; i += 256) g_SS[i] = 0.f;
        if (t == 0) { g_cut = 0.0; g_dt = 0.0; }
    }
    for (int e = tid; e < EE; e += stride) atomicAdd(&g_deg[col[e]], 1);
    for (int tb = bid; tb < 6250; tb += (int)G) {
        int v0 = (tb % 3125) * 32, k0 = (tb / 3125) * 32;
        int tx = t & 31, ty = t >> 5;
        __syncthreads();
        #pragma unroll
        for (int r = ty; r < 32; r += 8)
            s_tile[r][tx] = W[(size_t)(k0 + r) * NN + v0 + tx];
        __syncthreads();
        #pragma unroll
        for (int r = ty; r < 32; r += 8)
            g_Wh[(size_t)(v0 + r) * KE + k0 + tx] = __float2half(s_tile[tx][r]);
    }
    for (int idx = tid; idx < OC * INC; idx += stride) {
        int o = idx >> 7, c = idx & 127;
        float s = 0.f;
        for (int h = 0; h < HID; h++) s += finW[o * 320 + h] * mlpxW[h * INC + c];
        g_Wc[idx] = s;
    }
    if (tid < OC) {
        float s = finb[tid];
        for (int h = 0; h < HID; h++) s += finW[tid * 320 + h] * mlpxb[h];
        g_bc[tid] = s;
    }
    gsync(1u * G);

    // ================= P1: per-chunk scan (98 chunks of 1024) =================
    for (int c = bid; c < 98; c += (int)G) {
        int base = c * 1024 + t * 4;
        int v0 = (base + 0 < NN) ? g_deg[base + 0] : 0;
        int v1 = (base + 1 < NN) ? g_deg[base + 1] : 0;
        int v2 = (base + 2 < NN) ? g_deg[base + 2] : 0;
        int v3 = (base + 3 < NN) ? g_deg[base + 3] : 0;
        int s = v0 + v1 + v2 + v3;
        s_scan[t] = s; __syncthreads();
        for (int off = 1; off < 256; off <<= 1) {
            int xv = (t >= off) ? s_scan[t - off] : 0;
            __syncthreads();
            s_scan[t] += xv;
            __syncthreads();
        }
        int run = s_scan[t] - s;
        if (t == 255) g_bsum[c] = s_scan[255];
        if (base + 0 < NN) g_ptr[base + 0] = run; run += v0;
        if (base + 1 < NN) g_ptr[base + 1] = run; run += v1;
        if (base + 2 < NN) g_ptr[base + 2] = run; run += v2;
        if (base + 3 < NN) g_ptr[base + 3] = run;
    }
    gsync(2u * G);

    // ================= P2: redundant block-sum scan + apply offsets =================
    {
        int v = (t < 98) ? g_bsum[t] : 0;
        if (t < 128) s_scan[t] = v;
        __syncthreads();
        for (int off = 1; off < 128; off <<= 1) {
            int xv = 0;
            if (t < 128 && t >= off) xv = s_scan[t - off];
            __syncthreads();
            if (t < 128) s_scan[t] += xv;
            __syncthreads();
        }
        if (t < 128) s_exc[t] = s_scan[t] - v;
        __syncthreads();
        for (int i = tid; i < NN; i += stride) {
            int p = g_ptr[i] + s_exc[i >> 10];
            g_ptr[i] = p;
            g_pos[i] = p;
        }
        if (tid == 0) g_ptr[NN] = EE;
    }
    gsync(3u * G);

    // ================= P3: scatter edges into CSR =================
    for (int e = tid; e < EE; e += stride) {
        int p = atomicAdd(&g_pos[col[e]], 1);
        g_srt[p] = row[e];
    }
    gsync(4u * G);

    // ================= P4: SpMM1 + softmax + deg_term (half-warp/node) =================
    {
        int gw = tid >> 5, l = t & 31, wl = t >> 5;
        int h = l >> 4, q = l & 15;
        int nw = G * 8;
        const float2* F2 = (const float2*)g_Wh;   // 4 halves per elem; row stride 16
        float4 b4 = __ldg(&((const float4*)MLPb)[q]);
        double ddt = 0.0;
        for (int pw = gw; pw < NN / 2; pw += nw) {
            int w = pw * 2 + h;
            int s = g_ptr[w], e = g_ptr[w + 1];
            float a0 = 0.f, a1 = 0.f, a2 = 0.f, a3 = 0.f;
            int i = s;
            for (; i + 4 <= e; i += 4) {
                int s0 = __ldg(&g_srt[i]),     s1 = __ldg(&g_srt[i + 1]);
                int s2 = __ldg(&g_srt[i + 2]), s3 = __ldg(&g_srt[i + 3]);
                float2 u0 = __ldg(&F2[(size_t)s0 * 16 + q]);
                float2 u1 = __ldg(&F2[(size_t)s1 * 16 + q]);
                float2 u2 = __ldg(&F2[(size_t)s2 * 16 + q]);
                float2 u3 = __ldg(&F2[(size_t)s3 * 16 + q]);
                float2 p0 = __half22float2(*(__half2*)&u0.x), p1 = __half22float2(*(__half2*)&u0.y);
                float2 p2 = __half22float2(*(__half2*)&u1.x), p3 = __half22float2(*(__half2*)&u1.y);
                float2 p4 = __half22float2(*(__half2*)&u2.x), p5 = __half22float2(*(__half2*)&u2.y);
                float2 p6 = __half22float2(*(__half2*)&u3.x), p7 = __half22float2(*(__half2*)&u3.y);
                a0 += (p0.x + p2.x) + (p4.x + p6.x);
                a1 += (p0.y + p2.y) + (p4.y + p6.y);
                a2 += (p1.x + p3.x) + (p5.x + p7.x);
                a3 += (p1.y + p3.y) + (p5.y + p7.y);
            }
            for (; i < e; i++) {
                int s0 = __ldg(&g_srt[i]);
                float2 u = __ldg(&F2[(size_t)s0 * 16 + q]);
                float2 p0 = __half22float2(*(__half2*)&u.x), p1 = __half22float2(*(__half2*)&u.y);
                a0 += p0.x; a1 += p0.y; a2 += p1.x; a3 += p1.y;
            }
            a0 += b4.x; a1 += b4.y; a2 += b4.z; a3 += b4.w;
            float m = fmaxf(fmaxf(a0, a1), fmaxf(a2, a3));
            #pragma unroll
            for (int d = 8; d >= 1; d >>= 1) m = fmaxf(m, __shfl_xor_sync(0xffffffffu, m, d));
            float e0 = expf(a0 - m), e1 = expf(a1 - m), e2 = expf(a2 - m), e3 = expf(a3 - m);
            float sum = (e0 + e1) + (e2 + e3);
            #pragma unroll
            for (int d = 8; d >= 1; d >>= 1) sum += __shfl_xor_sync(0xffffffffu, sum, d);
            float inv = 1.f / sum;
            float v0 = e0 * inv, v1 = e1 * inv, v2 = e2 * inv, v3 = e3 * inv;
            float4 sv = make_float4(v0, v1, v2, v3);
            ((float4*)g_S)[(size_t)w * 16 + q] = sv;
            __half2 hx = __floats2half2_rn(v0, v1);
            __half2 hy = __floats2half2_rn(v2, v3);
            float2 hp = make_float2(*(float*)&hx, *(float*)&hy);
            ((float2*)g_Sh)[(size_t)w * 16 + q] = hp;
            float ssq = (v0 * v0 + v1 * v1) + (v2 * v2 + v3 * v3);
            #pragma unroll
            for (int d = 8; d >= 1; d >>= 1) ssq += __shfl_xor_sync(0xffffffffu, ssq, d);
            if (q == 0) ddt += (double)(e - s) * (double)ssq;
        }
        __syncthreads();
        if (q == 0) s_red[wl * 2 + h] = ddt;
        __syncthreads();
        if (t == 0) {
            double a = 0.0;
            #pragma unroll
            for (int z = 0; z < 16; z++) a += s_red[z];
            atomicAdd(&g_dt, a);
        }
    }
    gsync(5u * G);

    // ================= P5: SpMM2 + cut (half-warp/node) =================
    {
        int gw = tid >> 5, l = t & 31, wl = t >> 5;
        int h = l >> 4, q = l & 15;
        int nw = G * 8;
        const float2* F2 = (const float2*)g_Sh;
        double dcut = 0.0;
        for (int pw = gw; pw < NN / 2; pw += nw) {
            int w = pw * 2 + h;
            int s = g_ptr[w], e = g_ptr[w + 1];
            float a0 = 0.f, a1 = 0.f, a2 = 0.f, a3 = 0.f;
            int i = s;
            for (; i + 4 <= e; i += 4) {
                int s0 = __ldg(&g_srt[i]),     s1 = __ldg(&g_srt[i + 1]);
                int s2 = __ldg(&g_srt[i + 2]), s3 = __ldg(&g_srt[i + 3]);
                float2 u0 = __ldg(&F2[(size_t)s0 * 16 + q]);
                float2 u1 = __ldg(&F2[(size_t)s1 * 16 + q]);
                float2 u2 = __ldg(&F2[(size_t)s2 * 16 + q]);
                float2 u3 = __ldg(&F2[(size_t)s3 * 16 + q]);
                float2 p0 = __half22float2(*(__half2*)&u0.x), p1 = __half22float2(*(__half2*)&u0.y);
                float2 p2 = __half22float2(*(__half2*)&u1.x), p3 = __half22float2(*(__half2*)&u1.y);
                float2 p4 = __half22float2(*(__half2*)&u2.x), p5 = __half22float2(*(__half2*)&u2.y);
                float2 p6 = __half22float2(*(__half2*)&u3.x), p7 = __half22float2(*(__half2*)&u3.y);
                a0 += (p0.x + p2.x) + (p4.x + p6.x);
                a1 += (p0.y + p2.y) + (p4.y + p6.y);
                a2 += (p1.x + p3.x) + (p5.x + p7.x);
                a3 += (p1.y + p3.y) + (p5.y + p7.y);
            }
            for (; i < e; i++) {
                int s0 = __ldg(&g_srt[i]);
                float2 u = __ldg(&F2[(size_t)s0 * 16 + q]);
                float2 p0 = __half22float2(*(__half2*)&u.x), p1 = __half22float2(*(__half2*)&u.y);
                a0 += p0.x; a1 += p0.y; a2 += p1.x; a3 += p1.y;
            }
            float4 sc = ((const float4*)g_S)[(size_t)w * 16 + q];
            float dot = (a0 * sc.x + a1 * sc.y) + (a2 * sc.z + a3 * sc.w);
            #pragma unroll
            for (int d = 8; d >= 1; d >>= 1) dot += __shfl_xor_sync(0xffffffffu, dot, d);
            if (q == 0) dcut += (double)dot;
        }
        __syncthreads();
        if (q == 0) s_red[wl * 2 + h] = dcut;
        __syncthreads();
        if (t == 0) {
            double a = 0.0;
            #pragma unroll
            for (int z = 0; z < 16; z++) a += s_red[z];
            atomicAdd(&g_cut, a);
        }
    }
    gsync(6u * G);

    // ================= P6: SSmat (blocks < ssp) | final (rest) =================
    {
        int ssp = (G >= 512u) ? 256 : (int)(G / 2);
        if (bid < ssp) {
            int ti = t >> 4, tj = t & 15;
            float acc[4][4] = {};
            const float4* S4 = (const float4*)g_S;
            for (int rb = bid * 16; rb < NN; rb += ssp * 16) {
                __syncthreads();
                s_rows[t >> 4][t & 15] = S4[(size_t)(rb + (t >> 4)) * 16 + (t & 15)];
                __syncthreads();
                #pragma unroll 4
                for (int r = 0; r < 16; r++) {
                    float4 a = s_rows[r][ti];
                    float4 c = s_rows[r][tj];
                    acc[0][0] += a.x * c.x; acc[0][1] += a.x * c.y; acc[0][2] += a.x * c.z; acc[0][3] += a.x * c.w;
                    acc[1][0] += a.y * c.x; acc[1][1] += a.y * c.y; acc[1][2] += a.y * c.z; acc[1][3] += a.y * c.w;
                    acc[2][0] += a.z * c.x; acc[2][1] += a.z * c.y; acc[2][2] += a.z * c.z; acc[2][3] += a.z * c.w;
                    acc[3][0] += a.w * c.x; acc[3][1] += a.w * c.y; acc[3][2] += a.w * c.z; acc[3][3] += a.w * c.w;
                }
            }
            #pragma unroll
            for (int p = 0; p < 4; p++)
                #pragma unroll
                for (int qq = 0; qq < 4; qq++)
                    atomicAdd(&g_SS[(ti * 4 + p) * KE + tj * 4 + qq], acc[p][qq]);
        } else {
            for (int idx = t; idx < 512; idx += 256) {
                int c4 = idx >> 4, o = idx & 15;
                s_Wx[c4][o] = ((const float4*)g_Wc)[o * 32 + c4];
            }
            {
                int k4 = t >> 4, o = t & 15;
                s_Wa[k4][o] = ((const float4*)finW)[o * 80 + 64 + k4];
            }
            if (t < 16) s_bo[t] = g_bc[t];
            __syncthreads();
            const float4* x4 = (const float4*)x;
            const float4* S4 = (const float4*)g_S;
            for (int g = bid - ssp; g < 6250; g += (int)G - ssp) {
                int n = g * 16 + (t >> 4);
                int o = t & 15;
                float acc = s_bo[o];
                #pragma unroll 8
                for (int c4 = 0; c4 < 32; c4++) {
                    float4 xv = x4[(size_t)n * 32 + c4];
                    float4 wv = s_Wx[c4][o];
                    acc += xv.x * wv.x + xv.y * wv.y + xv.z * wv.z + xv.w * wv.w;
                }
                #pragma unroll 8
                for (int k4 = 0; k4 < 16; k4++) {
                    float4 sv = S4[(size_t)n * 16 + k4];
                    float4 wv = s_Wa[k4][o];
                    acc += sv.x * wv.x + sv.y * wv.y + sv.z * wv.z + sv.w * wv.w;
                }
                float m = acc;
                #pragma unroll
                for (int d = 1; d < 16; d <<= 1) m = fmaxf(m, __shfl_xor_sync(0xffffffffu, m, d));
                float ex = expf(acc - m);
                float sum = ex;
                #pragma unroll
                for (int d = 1; d < 16; d <<= 1) sum += __shfl_xor_sync(0xffffffffu, sum, d);
                out[(size_t)n * 16 + o] = acc - m - logf(sum);
            }
        }
    }
    gsync(7u * G);

    // ================= P7: loss (block 0) =================
    if (bid == 0) {
        double s = 0.0;
        for (int i = t; i < KE * KE; i += 256) { double v = (double)g_SS[i]; s += v * v; }
        s_loss[t] = s; __syncthreads();
        for (int off = 128; off >= 1; off >>= 1) { if (t < off) s_loss[t] += s_loss[t + off]; __syncthreads(); }
        if (t == 0) s_dnrm = sqrt(s_loss[0]);
        __syncthreads();
        double s2 = 0.0;
        for (int i = t; i < KE * KE; i += 256) {
            double v = (double)g_SS[i] / s_dnrm;
            if ((i >> 6) == (i & 63)) v -= 0.125;   // I / sqrt(64)
            s2 += v * v;
        }
        s_loss[t] = s2; __syncthreads();
        for (int off = 128; off >= 1; off >>= 1) { if (t < off) s_loss[t] += s_loss[t + off]; __syncthreads(); }
        if (t == 0) {
            double loss = -(g_cut / g_dt) + sqrt(s_loss[0]);
            out[outIdx] = (float)loss;
        }
    }
}

// ================================================================ launch
extern "C" void kernel_launch(void* const* d_in, const int* in_sizes, int n_in,
                              void* d_out, int out_size) {
    const float* x     = (const float*)d_in[0];
    const int*   ei    = (const int*)  d_in[1];
    const float* MLPW  = (const float*)d_in[2];
    const float* MLPb  = (const float*)d_in[3];
    const float* mlpxW = (const float*)d_in[4];
    const float* mlpxb = (const float*)d_in[5];
    const float* finW  = (const float*)d_in[6];
    const float* finb  = (const float*)d_in[7];
    float* out = (float*)d_out;

    const int* row = ei;
    const int* col = ei + EE;

    int nb = 0;
    cudaOccupancyMaxActiveBlocksPerMultiprocessor(&nb, k_persist, 256, 0);
    if (nb <= 0) nb = 1;
    int smc = 0;
    cudaDeviceGetAttribute(&smc, cudaDevAttrMultiProcessorCount, 0);
    if (smc <= 0) smc = 148;
    unsigned G = (unsigned)(nb * smc);
    if (G > 2048u) G = 2048u;

    void* degp = nullptr;  cudaGetSymbolAddress(&degp, g_deg);
    void* barp = nullptr;  cudaGetSymbolAddress(&barp, g_bar);
    cudaMemsetAsync(degp, 0, NN * sizeof(int));
    cudaMemsetAsync(barp, 0, sizeof(unsigned));

    k_persist<<<G, 256>>>(MLPW, row, col, MLPb, finW, mlpxW, mlpxb, finb, x, out,
                          out_size - 1);
}

// round 8
// speedup vs baseline: 1.1829x; 1.0013x over previous
#include <cuda_runtime.h>
#include <cuda_fp16.h>
#include <math.h>

#define NN 100000
#define EE 1600000
#define KE 64
#define INC 128
#define HID 256
#define OC 16

typedef unsigned long long ull;

// ---- static device scratch ----
__device__ __half  g_Wh[(size_t)NN * KE];  // MLP_W^T fp16 [N,64]
__device__ float   g_S [(size_t)NN * KE];  // S fp32
__device__ __half  g_Sh[(size_t)NN * KE];  // S fp16 (SpMM2 gather)
__device__ int     g_deg[NN];
__device__ int     g_ptr[NN + 1];
__device__ int     g_pos[NN];
__device__ int     g_srt[EE];
__device__ int     g_bsum[128];
__device__ float   g_SS[KE * KE];
__device__ float   g_Wc[OC * INC];
__device__ float   g_bc[OC];
__device__ double  g_cut;
__device__ double  g_dt;
__device__ volatile unsigned g_bar;

// ---- software grid barrier: grid <= guaranteed-resident blocks ----
__device__ __forceinline__ void gsync(unsigned target) {
    __syncthreads();
    if (threadIdx.x == 0) {
        __threadfence();
        atomicAdd((unsigned*)&g_bar, 1u);
        while (g_bar < target) __nanosleep(64);
        __threadfence();
    }
    __syncthreads();
}

__device__ __forceinline__ void cvt8(float4 u, float* p) {
    float2 c0 = __half22float2(*(__half2*)&u.x);
    float2 c1 = __half22float2(*(__half2*)&u.y);
    float2 c2 = __half22float2(*(__half2*)&u.z);
    float2 c3 = __half22float2(*(__half2*)&u.w);
    p[0] = c0.x; p[1] = c0.y; p[2] = c1.x; p[3] = c1.y;
    p[4] = c2.x; p[5] = c2.y; p[6] = c3.x; p[7] = c3.y;
}

__global__ void __launch_bounds__(256) k_persist(
    const float* __restrict__ W,        // MLP_W [64,N]
    const int*   __restrict__ row,
    const int*   __restrict__ col,
    const float* __restrict__ MLPb,
    const float* __restrict__ finW,
    const float* __restrict__ mlpxW,
    const float* __restrict__ mlpxb,
    const float* __restrict__ finb,
    const float* __restrict__ x,
    float*       __restrict__ out,
    int outIdx)
{
    const unsigned G = gridDim.x;
    const int bid = blockIdx.x;
    const int t   = threadIdx.x;
    const int tid = bid * 256 + t;
    const int stride = G * 256;

    __shared__ float  s_tile[32][33];
    __shared__ int    s_scan[256];
    __shared__ int    s_exc[128];
    __shared__ double s_red[32];
    __shared__ float4 s_rows[16][16];
    __shared__ float4 s_Wx[32][16];
    __shared__ float4 s_Wa[16][16];
    __shared__ float  s_bo[16];
    __shared__ double s_loss[256];
    __shared__ double s_dnrm;

    // ================= P0: hist | transpose->fp16 | wcomb | zero small =================
    if (bid == 0) {
        for (int i = t; i < KE * KE; i += 256) g_SS[i] = 0.f;
        if (t == 0) { g_cut = 0.0; g_dt = 0.0; }
    }
    for (int e = tid; e < EE; e += stride) atomicAdd(&g_deg[col[e]], 1);
    for (int tb = bid; tb < 6250; tb += (int)G) {
        int v0 = (tb % 3125) * 32, k0 = (tb / 3125) * 32;
        int tx = t & 31, ty = t >> 5;
        __syncthreads();
        #pragma unroll
        for (int r = ty; r < 32; r += 8)
            s_tile[r][tx] = W[(size_t)(k0 + r) * NN + v0 + tx];
        __syncthreads();
        #pragma unroll
        for (int r = ty; r < 32; r += 8)
            g_Wh[(size_t)(v0 + r) * KE + k0 + tx] = __float2half(s_tile[tx][r]);
    }
    for (int idx = tid; idx < OC * INC; idx += stride) {
        int o = idx >> 7, c = idx & 127;
        float s = 0.f;
        for (int h = 0; h < HID; h++) s += finW[o * 320 + h] * mlpxW[h * INC + c];
        g_Wc[idx] = s;
    }
    if (tid < OC) {
        float s = finb[tid];
        for (int h = 0; h < HID; h++) s += finW[tid * 320 + h] * mlpxb[h];
        g_bc[tid] = s;
    }
    gsync(1u * G);

    // ================= P1: per-chunk scan (98 chunks of 1024) =================
    for (int c = bid; c < 98; c += (int)G) {
        int base = c * 1024 + t * 4;
        int v0 = (base + 0 < NN) ? g_deg[base + 0] : 0;
        int v1 = (base + 1 < NN) ? g_deg[base + 1] : 0;
        int v2 = (base + 2 < NN) ? g_deg[base + 2] : 0;
        int v3 = (base + 3 < NN) ? g_deg[base + 3] : 0;
        int s = v0 + v1 + v2 + v3;
        s_scan[t] = s; __syncthreads();
        for (int off = 1; off < 256; off <<= 1) {
            int xv = (t >= off) ? s_scan[t - off] : 0;
            __syncthreads();
            s_scan[t] += xv;
            __syncthreads();
        }
        int run = s_scan[t] - s;
        if (t == 255) g_bsum[c] = s_scan[255];
        if (base + 0 < NN) g_ptr[base + 0] = run; run += v0;
        if (base + 1 < NN) g_ptr[base + 1] = run; run += v1;
        if (base + 2 < NN) g_ptr[base + 2] = run; run += v2;
        if (base + 3 < NN) g_ptr[base + 3] = run;
    }
    gsync(2u * G);

    // ================= P2: redundant block-sum scan + apply offsets =================
    {
        int v = (t < 98) ? g_bsum[t] : 0;
        if (t < 128) s_scan[t] = v;
        __syncthreads();
        for (int off = 1; off < 128; off <<= 1) {
            int xv = 0;
            if (t < 128 && t >= off) xv = s_scan[t - off];
            __syncthreads();
            if (t < 128) s_scan[t] += xv;
            __syncthreads();
        }
        if (t < 128) s_exc[t] = s_scan[t] - v;
        __syncthreads();
        for (int i = tid; i < NN; i += stride) {
            int p = g_ptr[i] + s_exc[i >> 10];
            g_ptr[i] = p;
            g_pos[i] = p;
        }
        if (tid == 0) g_ptr[NN] = EE;
    }
    gsync(3u * G);

    // ================= P3: scatter edges into CSR =================
    for (int e = tid; e < EE; e += stride) {
        int p = atomicAdd(&g_pos[col[e]], 1);
        g_srt[p] = row[e];
    }
    gsync(4u * G);

    // ================= P4: SpMM1 + softmax + deg_term (quarter-warp/node) =================
    {
        int gw = tid >> 5, l = t & 31, wl = t >> 5;
        int h = l >> 3, q = l & 7;                 // 4 nodes/warp, 8 lanes/node
        int nw = G * 8;
        const float4* F4 = (const float4*)g_Wh;    // row = 8 float4 (64 halves)
        float4 bq0 = __ldg(&((const float4*)MLPb)[q * 2]);
        float4 bq1 = __ldg(&((const float4*)MLPb)[q * 2 + 1]);
        double ddt = 0.0;
        for (int pw = gw; pw < NN / 4; pw += nw) {
            int w = pw * 4 + h;
            int s = g_ptr[w], e = g_ptr[w + 1];
            float a[8] = {};
            int i = s;
            for (; i + 4 <= e; i += 4) {
                int s0 = __ldg(&g_srt[i]),     s1 = __ldg(&g_srt[i + 1]);
                int s2 = __ldg(&g_srt[i + 2]), s3 = __ldg(&g_srt[i + 3]);
                float4 u0 = __ldg(&F4[(size_t)s0 * 8 + q]);
                float4 u1 = __ldg(&F4[(size_t)s1 * 8 + q]);
                float4 u2 = __ldg(&F4[(size_t)s2 * 8 + q]);
                float4 u3 = __ldg(&F4[(size_t)s3 * 8 + q]);
                float p0[8], p1[8], p2[8], p3[8];
                cvt8(u0, p0); cvt8(u1, p1); cvt8(u2, p2); cvt8(u3, p3);
                #pragma unroll
                for (int k = 0; k < 8; k++) a[k] += (p0[k] + p1[k]) + (p2[k] + p3[k]);
            }
            for (; i < e; i++) {
                int s0 = __ldg(&g_srt[i]);
                float4 u = __ldg(&F4[(size_t)s0 * 8 + q]);
                float p[8];
                cvt8(u, p);
                #pragma unroll
                for (int k = 0; k < 8; k++) a[k] += p[k];
            }
            a[0] += bq0.x; a[1] += bq0.y; a[2] += bq0.z; a[3] += bq0.w;
            a[4] += bq1.x; a[5] += bq1.y; a[6] += bq1.z; a[7] += bq1.w;
            float m = a[0];
            #pragma unroll
            for (int k = 1; k < 8; k++) m = fmaxf(m, a[k]);
            #pragma unroll
            for (int d = 4; d >= 1; d >>= 1) m = fmaxf(m, __shfl_xor_sync(0xffffffffu, m, d));
            float ex[8], sum = 0.f;
            #pragma unroll
            for (int k = 0; k < 8; k++) { ex[k] = expf(a[k] - m); sum += ex[k]; }
            #pragma unroll
            for (int d = 4; d >= 1; d >>= 1) sum += __shfl_xor_sync(0xffffffffu, sum, d);
            float inv = 1.f / sum;
            float v[8];
            float ssq = 0.f;
            #pragma unroll
            for (int k = 0; k < 8; k++) { v[k] = ex[k] * inv; ssq += v[k] * v[k]; }
            ((float4*)g_S)[(size_t)w * 16 + q * 2]     = make_float4(v[0], v[1], v[2], v[3]);
            ((float4*)g_S)[(size_t)w * 16 + q * 2 + 1] = make_float4(v[4], v[5], v[6], v[7]);
            __half2 h0 = __floats2half2_rn(v[0], v[1]);
            __half2 h1 = __floats2half2_rn(v[2], v[3]);
            __half2 h2 = __floats2half2_rn(v[4], v[5]);
            __half2 h3 = __floats2half2_rn(v[6], v[7]);
            ((float4*)g_Sh)[(size_t)w * 8 + q] =
                make_float4(*(float*)&h0, *(float*)&h1, *(float*)&h2, *(float*)&h3);
            #pragma unroll
            for (int d = 4; d >= 1; d >>= 1) ssq += __shfl_xor_sync(0xffffffffu, ssq, d);
            if (q == 0) ddt += (double)(e - s) * (double)ssq;
        }
        __syncthreads();
        if (q == 0) s_red[wl * 4 + h] = ddt;
        __syncthreads();
        if (t == 0) {
            double a = 0.0;
            #pragma unroll
            for (int z = 0; z < 32; z++) a += s_red[z];
            atomicAdd(&g_dt, a);
        }
    }
    gsync(5u * G);

    // ================= P5: SpMM2 + cut (quarter-warp/node) =================
    {
        int gw = tid >> 5, l = t & 31, wl = t >> 5;
        int h = l >> 3, q = l & 7;
        int nw = G * 8;
        const float4* F4 = (const float4*)g_Sh;
        double dcut = 0.0;
        for (int pw = gw; pw < NN / 4; pw += nw) {
            int w = pw * 4 + h;
            int s = g_ptr[w], e = g_ptr[w + 1];
            float a[8] = {};
            int i = s;
            for (; i + 4 <= e; i += 4) {
                int s0 = __ldg(&g_srt[i]),     s1 = __ldg(&g_srt[i + 1]);
                int s2 = __ldg(&g_srt[i + 2]), s3 = __ldg(&g_srt[i + 3]);
                float4 u0 = __ldg(&F4[(size_t)s0 * 8 + q]);
                float4 u1 = __ldg(&F4[(size_t)s1 * 8 + q]);
                float4 u2 = __ldg(&F4[(size_t)s2 * 8 + q]);
                float4 u3 = __ldg(&F4[(size_t)s3 * 8 + q]);
                float p0[8], p1[8], p2[8], p3[8];
                cvt8(u0, p0); cvt8(u1, p1); cvt8(u2, p2); cvt8(u3, p3);
                #pragma unroll
                for (int k = 0; k < 8; k++) a[k] += (p0[k] + p1[k]) + (p2[k] + p3[k]);
            }
            for (; i < e; i++) {
                int s0 = __ldg(&g_srt[i]);
                float4 u = __ldg(&F4[(size_t)s0 * 8 + q]);
                float p[8];
                cvt8(u, p);
                #pragma unroll
                for (int k = 0; k < 8; k++) a[k] += p[k];
            }
            float4 sc0 = ((const float4*)g_S)[(size_t)w * 16 + q * 2];
            float4 sc1 = ((const float4*)g_S)[(size_t)w * 16 + q * 2 + 1];
            float dot = (a[0] * sc0.x + a[1] * sc0.y) + (a[2] * sc0.z + a[3] * sc0.w)
                      + (a[4] * sc1.x + a[5] * sc1.y) + (a[6] * sc1.z + a[7] * sc1.w);
            #pragma unroll
            for (int d = 4; d >= 1; d >>= 1) dot += __shfl_xor_sync(0xffffffffu, dot, d);
            if (q == 0) dcut += (double)dot;
        }
        __syncthreads();
        if (q == 0) s_red[wl * 4 + h] = dcut;
        __syncthreads();
        if (t == 0) {
            double a = 0.0;
            #pragma unroll
            for (int z = 0; z < 32; z++) a += s_red[z];
            atomicAdd(&g_cut, a);
        }
    }
    gsync(6u * G);

    // ================= P6: SSmat (blocks < ssp) | final (rest) =================
    {
        int ssp = (G >= 512u) ? 256 : (int)(G / 2);
        if (bid < ssp) {
            int ti = t >> 4, tj = t & 15;
            float acc[4][4] = {};
            const float4* S4 = (const float4*)g_S;
            for (int rb = bid * 16; rb < NN; rb += ssp * 16) {
                __syncthreads();
                s_rows[t >> 4][t & 15] = S4[(size_t)(rb + (t >> 4)) * 16 + (t & 15)];
                __syncthreads();
                #pragma unroll 4
                for (int r = 0; r < 16; r++) {
                    float4 a = s_rows[r][ti];
                    float4 c = s_rows[r][tj];
                    acc[0][0] += a.x * c.x; acc[0][1] += a.x * c.y; acc[0][2] += a.x * c.z; acc[0][3] += a.x * c.w;
                    acc[1][0] += a.y * c.x; acc[1][1] += a.y * c.y; acc[1][2] += a.y * c.z; acc[1][3] += a.y * c.w;
                    acc[2][0] += a.z * c.x; acc[2][1] += a.z * c.y; acc[2][2] += a.z * c.z; acc[2][3] += a.z * c.w;
                    acc[3][0] += a.w * c.x; acc[3][1] += a.w * c.y; acc[3][2] += a.w * c.z; acc[3][3] += a.w * c.w;
                }
            }
            #pragma unroll
            for (int p = 0; p < 4; p++)
                #pragma unroll
                for (int qq = 0; qq < 4; qq++)
                    atomicAdd(&g_SS[(ti * 4 + p) * KE + tj * 4 + qq], acc[p][qq]);
        } else {
            for (int idx = t; idx < 512; idx += 256) {
                int c4 = idx >> 4, o = idx & 15;
                s_Wx[c4][o] = ((const float4*)g_Wc)[o * 32 + c4];
            }
            {
                int k4 = t >> 4, o = t & 15;
                s_Wa[k4][o] = ((const float4*)finW)[o * 80 + 64 + k4];
            }
            if (t < 16) s_bo[t] = g_bc[t];
            __syncthreads();
            const float4* x4 = (const float4*)x;
            const float4* S4 = (const float4*)g_S;
            for (int g = bid - ssp; g < 6250; g += (int)G - ssp) {
                int n = g * 16 + (t >> 4);
                int o = t & 15;
                float acc = s_bo[o];
                #pragma unroll 8
                for (int c4 = 0; c4 < 32; c4++) {
                    float4 xv = x4[(size_t)n * 32 + c4];
                    float4 wv = s_Wx[c4][o];
                    acc += xv.x * wv.x + xv.y * wv.y + xv.z * wv.z + xv.w * wv.w;
                }
                #pragma unroll 8
                for (int k4 = 0; k4 < 16; k4++) {
                    float4 sv = S4[(size_t)n * 16 + k4];
                    float4 wv = s_Wa[k4][o];
                    acc += sv.x * wv.x + sv.y * wv.y + sv.z * wv.z + sv.w * wv.w;
                }
                float m = acc;
                #pragma unroll
                for (int d = 1; d < 16; d <<= 1) m = fmaxf(m, __shfl_xor_sync(0xffffffffu, m, d));
                float ex = expf(acc - m);
                float sum = ex;
                #pragma unroll
                for (int d = 1; d < 16; d <<= 1) sum += __shfl_xor_sync(0xffffffffu, sum, d);
                out[(size_t)n * 16 + o] = acc - m - logf(sum);
            }
        }
    }
    gsync(7u * G);

    // ================= P7: loss (block 0) =================
    if (bid == 0) {
        double s = 0.0;
        for (int i = t; i < KE * KE; i += 256) { double v = (double)g_SS[i]; s += v * v; }
        s_loss[t] = s; __syncthreads();
        for (int off = 128; off >= 1; off >>= 1) { if (t < off) s_loss[t] += s_loss[t + off]; __syncthreads(); }
        if (t == 0) s_dnrm = sqrt(s_loss[0]);
        __syncthreads();
        double s2 = 0.0;
        for (int i = t; i < KE * KE; i += 256) {
            double v = (double)g_SS[i] / s_dnrm;
            if ((i >> 6) == (i & 63)) v -= 0.125;   // I / sqrt(64)
            s2 += v * v;
        }
        s_loss[t] = s2; __syncthreads();
        for (int off = 128; off >= 1; off >>= 1) { if (t < off) s_loss[t] += s_loss[t + off]; __syncthreads(); }
        if (t == 0) {
            double loss = -(g_cut / g_dt) + sqrt(s_loss[0]);
            out[outIdx] = (float)loss;
        }
    }
}

// ================================================================ launch
extern "C" void kernel_launch(void* const* d_in, const int* in_sizes, int n_in,
                              void* d_out, int out_size) {
    const float* x     = (const float*)d_in[0];
    const int*   ei    = (const int*)  d_in[1];
    const float* MLPW  = (const float*)d_in[2];
    const float* MLPb  = (const float*)d_in[3];
    const float* mlpxW = (const float*)d_in[4];
    const float* mlpxb = (const float*)d_in[5];
    const float* finW  = (const float*)d_in[6];
    const float* finb  = (const float*)d_in[7];
    float* out = (float*)d_out;

    const int* row = ei;
    const int* col = ei + EE;

    int nb = 0;
    cudaOccupancyMaxActiveBlocksPerMultiprocessor(&nb, k_persist, 256, 0);
    if (nb <= 0) nb = 1;
    int smc = 0;
    cudaDeviceGetAttribute(&smc, cudaDevAttrMultiProcessorCount, 0);
    if (smc <= 0) smc = 148;
    unsigned G = (unsigned)(nb * smc);
    if (G > 2048u) G = 2048u;

    void* degp = nullptr;  cudaGetSymbolAddress(&degp, g_deg);
    void* barp = nullptr;  cudaGetSymbolAddress(&barp, g_bar);
    cudaMemsetAsync(degp, 0, NN * sizeof(int));
    cudaMemsetAsync(barp, 0, sizeof(unsigned));

    k_persist<<<G, 256>>>(MLPW, row, col, MLPb, finW, mlpxW, mlpxb, finb, x, out,
                          out_size - 1);
}

// round 9
// speedup vs baseline: 1.2007x; 1.0151x over previous
#include <cuda_runtime.h>
#include <cuda_fp16.h>
#include <math.h>

#define NN 100000
#define EE 1600000
#define KE 64
#define INC 128
#define HID 256
#define OC 16

typedef unsigned long long ull;

// ---- static device scratch ----
__device__ __half  g_Wh[(size_t)NN * KE];  // MLP_W^T fp16 [N,64]
__device__ float   g_S [(size_t)NN * KE];  // S fp32
__device__ __half  g_Sh[(size_t)NN * KE];  // S fp16 (cut-phase gather)
__device__ int     g_deg[NN];
__device__ int     g_ptr[NN + 1];
__device__ int     g_pos[NN];
__device__ int     g_srt[EE];
__device__ int     g_bsum[128];
__device__ float   g_SS[KE * KE];
__device__ float   g_Wc[OC * INC];
__device__ float   g_bc[OC];
__device__ double  g_cut;
__device__ double  g_dt;
__device__ volatile unsigned g_bar;

// ---- software grid barrier: grid <= guaranteed-resident blocks ----
__device__ __forceinline__ void gsync(unsigned target) {
    __syncthreads();
    if (threadIdx.x == 0) {
        __threadfence();
        atomicAdd((unsigned*)&g_bar, 1u);
        while (g_bar < target) __nanosleep(64);
        __threadfence();
    }
    __syncthreads();
}

__device__ __forceinline__ void cvt8(float4 u, float* p) {
    float2 c0 = __half22float2(*(__half2*)&u.x);
    float2 c1 = __half22float2(*(__half2*)&u.y);
    float2 c2 = __half22float2(*(__half2*)&u.z);
    float2 c3 = __half22float2(*(__half2*)&u.w);
    p[0] = c0.x; p[1] = c0.y; p[2] = c1.x; p[3] = c1.y;
    p[4] = c2.x; p[5] = c2.y; p[6] = c3.x; p[7] = c3.y;
}

__global__ void __launch_bounds__(256) k_persist(
    const float* __restrict__ W,        // MLP_W [64,N]
    const int*   __restrict__ row,
    const int*   __restrict__ col,
    const float* __restrict__ MLPb,
    const float* __restrict__ finW,
    const float* __restrict__ mlpxW,
    const float* __restrict__ mlpxb,
    const float* __restrict__ finb,
    const float* __restrict__ x,
    float*       __restrict__ out,
    int outIdx)
{
    const unsigned G = gridDim.x;
    const int bid = blockIdx.x;
    const int t   = threadIdx.x;
    const int tid = bid * 256 + t;
    const int stride = G * 256;

    __shared__ float  s_tile[32][33];
    __shared__ int    s_scan[256];
    __shared__ int    s_exc[128];
    __shared__ double s_red[32];
    __shared__ float4 s_rows[16][16];
    __shared__ float4 s_Wx[32][16];
    __shared__ float4 s_Wa[16][16];
    __shared__ float  s_bo[16];
    __shared__ double s_loss[256];
    __shared__ double s_dnrm;

    // ================= P0: hist | transpose->fp16 | wcomb | zero small =================
    if (bid == 0) {
        for (int i = t; i < KE * KE; i += 256) g_SS[i] = 0.f;
        if (t == 0) { g_cut = 0.0; g_dt = 0.0; }
    }
    for (int e = tid; e < EE; e += stride) atomicAdd(&g_deg[col[e]], 1);
    for (int tb = bid; tb < 6250; tb += (int)G) {
        int v0 = (tb % 3125) * 32, k0 = (tb / 3125) * 32;
        int tx = t & 31, ty = t >> 5;
        __syncthreads();
        #pragma unroll
        for (int r = ty; r < 32; r += 8)
            s_tile[r][tx] = W[(size_t)(k0 + r) * NN + v0 + tx];
        __syncthreads();
        #pragma unroll
        for (int r = ty; r < 32; r += 8)
            g_Wh[(size_t)(v0 + r) * KE + k0 + tx] = __float2half(s_tile[tx][r]);
    }
    for (int idx = tid; idx < OC * INC; idx += stride) {
        int o = idx >> 7, c = idx & 127;
        float s = 0.f;
        for (int h = 0; h < HID; h++) s += finW[o * 320 + h] * mlpxW[h * INC + c];
        g_Wc[idx] = s;
    }
    if (tid < OC) {
        float s = finb[tid];
        for (int h = 0; h < HID; h++) s += finW[tid * 320 + h] * mlpxb[h];
        g_bc[tid] = s;
    }
    gsync(1u * G);

    // ================= P1: per-chunk scan (98 chunks of 1024) =================
    for (int c = bid; c < 98; c += (int)G) {
        int base = c * 1024 + t * 4;
        int v0 = (base + 0 < NN) ? g_deg[base + 0] : 0;
        int v1 = (base + 1 < NN) ? g_deg[base + 1] : 0;
        int v2 = (base + 2 < NN) ? g_deg[base + 2] : 0;
        int v3 = (base + 3 < NN) ? g_deg[base + 3] : 0;
        int s = v0 + v1 + v2 + v3;
        s_scan[t] = s; __syncthreads();
        for (int off = 1; off < 256; off <<= 1) {
            int xv = (t >= off) ? s_scan[t - off] : 0;
            __syncthreads();
            s_scan[t] += xv;
            __syncthreads();
        }
        int run = s_scan[t] - s;
        if (t == 255) g_bsum[c] = s_scan[255];
        if (base + 0 < NN) g_ptr[base + 0] = run; run += v0;
        if (base + 1 < NN) g_ptr[base + 1] = run; run += v1;
        if (base + 2 < NN) g_ptr[base + 2] = run; run += v2;
        if (base + 3 < NN) g_ptr[base + 3] = run;
    }
    gsync(2u * G);

    // ================= P2: redundant block-sum scan + apply offsets =================
    {
        int v = (t < 98) ? g_bsum[t] : 0;
        if (t < 128) s_scan[t] = v;
        __syncthreads();
        for (int off = 1; off < 128; off <<= 1) {
            int xv = 0;
            if (t < 128 && t >= off) xv = s_scan[t - off];
            __syncthreads();
            if (t < 128) s_scan[t] += xv;
            __syncthreads();
        }
        if (t < 128) s_exc[t] = s_scan[t] - v;
        __syncthreads();
        for (int i = tid; i < NN; i += stride) {
            int p = g_ptr[i] + s_exc[i >> 10];
            g_ptr[i] = p;
            g_pos[i] = p;
        }
        if (tid == 0) g_ptr[NN] = EE;
    }
    gsync(3u * G);

    // ================= P3: scatter edges into CSR =================
    for (int e = tid; e < EE; e += stride) {
        int p = atomicAdd(&g_pos[col[e]], 1);
        g_srt[p] = row[e];
    }
    gsync(4u * G);

    // ================= P4: SpMM1 + softmax + deg_term (quarter-warp/node) =================
    {
        int gw = tid >> 5, l = t & 31, wl = t >> 5;
        int h = l >> 3, q = l & 7;                 // 4 nodes/warp, 8 lanes/node
        int nw = G * 8;
        const float4* F4 = (const float4*)g_Wh;    // row = 8 float4 (64 halves)
        float4 bq0 = __ldg(&((const float4*)MLPb)[q * 2]);
        float4 bq1 = __ldg(&((const float4*)MLPb)[q * 2 + 1]);
        double ddt = 0.0;
        for (int pw = gw; pw < NN / 4; pw += nw) {
            int w = pw * 4 + h;
            int s = g_ptr[w], e = g_ptr[w + 1];
            float a[8] = {};
            int i = s;
            for (; i + 4 <= e; i += 4) {
                int s0 = __ldg(&g_srt[i]),     s1 = __ldg(&g_srt[i + 1]);
                int s2 = __ldg(&g_srt[i + 2]), s3 = __ldg(&g_srt[i + 3]);
                float4 u0 = __ldg(&F4[(size_t)s0 * 8 + q]);
                float4 u1 = __ldg(&F4[(size_t)s1 * 8 + q]);
                float4 u2 = __ldg(&F4[(size_t)s2 * 8 + q]);
                float4 u3 = __ldg(&F4[(size_t)s3 * 8 + q]);
                float p0[8], p1[8], p2[8], p3[8];
                cvt8(u0, p0); cvt8(u1, p1); cvt8(u2, p2); cvt8(u3, p3);
                #pragma unroll
                for (int k = 0; k < 8; k++) a[k] += (p0[k] + p1[k]) + (p2[k] + p3[k]);
            }
            for (; i < e; i++) {
                int s0 = __ldg(&g_srt[i]);
                float4 u = __ldg(&F4[(size_t)s0 * 8 + q]);
                float p[8];
                cvt8(u, p);
                #pragma unroll
                for (int k = 0; k < 8; k++) a[k] += p[k];
            }
            a[0] += bq0.x; a[1] += bq0.y; a[2] += bq0.z; a[3] += bq0.w;
            a[4] += bq1.x; a[5] += bq1.y; a[6] += bq1.z; a[7] += bq1.w;
            float m = a[0];
            #pragma unroll
            for (int k = 1; k < 8; k++) m = fmaxf(m, a[k]);
            #pragma unroll
            for (int d = 4; d >= 1; d >>= 1) m = fmaxf(m, __shfl_xor_sync(0xffffffffu, m, d));
            float ex[8], sum = 0.f;
            #pragma unroll
            for (int k = 0; k < 8; k++) { ex[k] = expf(a[k] - m); sum += ex[k]; }
            #pragma unroll
            for (int d = 4; d >= 1; d >>= 1) sum += __shfl_xor_sync(0xffffffffu, sum, d);
            float inv = 1.f / sum;
            float v[8];
            float ssq = 0.f;
            #pragma unroll
            for (int k = 0; k < 8; k++) { v[k] = ex[k] * inv; ssq += v[k] * v[k]; }
            ((float4*)g_S)[(size_t)w * 16 + q * 2]     = make_float4(v[0], v[1], v[2], v[3]);
            ((float4*)g_S)[(size_t)w * 16 + q * 2 + 1] = make_float4(v[4], v[5], v[6], v[7]);
            __half2 h0 = __floats2half2_rn(v[0], v[1]);
            __half2 h1 = __floats2half2_rn(v[2], v[3]);
            __half2 h2 = __floats2half2_rn(v[4], v[5]);
            __half2 h3 = __floats2half2_rn(v[6], v[7]);
            ((float4*)g_Sh)[(size_t)w * 8 + q] =
                make_float4(*(float*)&h0, *(float*)&h1, *(float*)&h2, *(float*)&h3);
            #pragma unroll
            for (int d = 4; d >= 1; d >>= 1) ssq += __shfl_xor_sync(0xffffffffu, ssq, d);
            if (q == 0) ddt += (double)(e - s) * (double)ssq;
        }
        __syncthreads();
        if (q == 0) s_red[wl * 4 + h] = ddt;
        __syncthreads();
        if (t == 0) {
            double a = 0.0;
            #pragma unroll
            for (int z = 0; z < 32; z++) a += s_red[z];
            atomicAdd(&g_dt, a);
        }
    }
    gsync(5u * G);

    // ================= P5: cut = sum_e S[row_e] . S[col_e]  (edge-parallel, 8 lanes/edge) =================
    {
        int q = t & 7;                        // lane within 8-lane group
        int gq = tid >> 3;                    // global group id
        int ngr = (int)G * 32;                // total groups
        const float4* F4 = (const float4*)g_Sh;
        float acc = 0.f;
        for (int e = gq; e < EE; e += ngr) {
            int r = __ldg(&row[e]);
            int c = __ldg(&col[e]);
            float4 u = __ldg(&F4[(size_t)r * 8 + q]);
            float4 v = __ldg(&F4[(size_t)c * 8 + q]);
            float pu[8], pv[8];
            cvt8(u, pu); cvt8(v, pv);
            float d = 0.f;
            #pragma unroll
            for (int k = 0; k < 8; k++) d += pu[k] * pv[k];
            acc += d;
        }
        // single end-of-phase warp reduction (all 32 lanes hold partials)
        #pragma unroll
        for (int d = 16; d >= 1; d >>= 1) acc += __shfl_xor_sync(0xffffffffu, acc, d);
        __syncthreads();
        if ((t & 31) == 0) s_red[t >> 5] = (double)acc;
        __syncthreads();
        if (t == 0) {
            double a = 0.0;
            #pragma unroll
            for (int z = 0; z < 8; z++) a += s_red[z];
            atomicAdd(&g_cut, a);
        }
    }
    gsync(6u * G);

    // ================= P6: SSmat (blocks < ssp) | final (rest) =================
    {
        int ssp = (G >= 512u) ? 256 : (int)(G / 2);
        if (bid < ssp) {
            int ti = t >> 4, tj = t & 15;
            float acc[4][4] = {};
            const float4* S4 = (const float4*)g_S;
            for (int rb = bid * 16; rb < NN; rb += ssp * 16) {
                __syncthreads();
                s_rows[t >> 4][t & 15] = S4[(size_t)(rb + (t >> 4)) * 16 + (t & 15)];
                __syncthreads();
                #pragma unroll 4
                for (int r = 0; r < 16; r++) {
                    float4 a = s_rows[r][ti];
                    float4 c = s_rows[r][tj];
                    acc[0][0] += a.x * c.x; acc[0][1] += a.x * c.y; acc[0][2] += a.x * c.z; acc[0][3] += a.x * c.w;
                    acc[1][0] += a.y * c.x; acc[1][1] += a.y * c.y; acc[1][2] += a.y * c.z; acc[1][3] += a.y * c.w;
                    acc[2][0] += a.z * c.x; acc[2][1] += a.z * c.y; acc[2][2] += a.z * c.z; acc[2][3] += a.z * c.w;
                    acc[3][0] += a.w * c.x; acc[3][1] += a.w * c.y; acc[3][2] += a.w * c.z; acc[3][3] += a.w * c.w;
                }
            }
            #pragma unroll
            for (int p = 0; p < 4; p++)
                #pragma unroll
                for (int qq = 0; qq < 4; qq++)
                    atomicAdd(&g_SS[(ti * 4 + p) * KE + tj * 4 + qq], acc[p][qq]);
        } else {
            for (int idx = t; idx < 512; idx += 256) {
                int c4 = idx >> 4, o = idx & 15;
                s_Wx[c4][o] = ((const float4*)g_Wc)[o * 32 + c4];
            }
            {
                int k4 = t >> 4, o = t & 15;
                s_Wa[k4][o] = ((const float4*)finW)[o * 80 + 64 + k4];
            }
            if (t < 16) s_bo[t] = g_bc[t];
            __syncthreads();
            const float4* x4 = (const float4*)x;
            const float4* S4 = (const float4*)g_S;
            for (int g = bid - ssp; g < 6250; g += (int)G - ssp) {
                int n = g * 16 + (t >> 4);
                int o = t & 15;
                float acc = s_bo[o];
                #pragma unroll 8
                for (int c4 = 0; c4 < 32; c4++) {
                    float4 xv = x4[(size_t)n * 32 + c4];
                    float4 wv = s_Wx[c4][o];
                    acc += xv.x * wv.x + xv.y * wv.y + xv.z * wv.z + xv.w * wv.w;
                }
                #pragma unroll 8
                for (int k4 = 0; k4 < 16; k4++) {
                    float4 sv = S4[(size_t)n * 16 + k4];
                    float4 wv = s_Wa[k4][o];
                    acc += sv.x * wv.x + sv.y * wv.y + sv.z * wv.z + sv.w * wv.w;
                }
                float m = acc;
                #pragma unroll
                for (int d = 1; d < 16; d <<= 1) m = fmaxf(m, __shfl_xor_sync(0xffffffffu, m, d));
                float ex = expf(acc - m);
                float sum = ex;
                #pragma unroll
                for (int d = 1; d < 16; d <<= 1) sum += __shfl_xor_sync(0xffffffffu, sum, d);
                out[(size_t)n * 16 + o] = acc - m - logf(sum);
            }
        }
    }
    gsync(7u * G);

    // ================= P7: loss (block 0) =================
    if (bid == 0) {
        double s = 0.0;
        for (int i = t; i < KE * KE; i += 256) { double v = (double)g_SS[i]; s += v * v; }
        s_loss[t] = s; __syncthreads();
        for (int off = 128; off >= 1; off >>= 1) { if (t < off) s_loss[t] += s_loss[t + off]; __syncthreads(); }
        if (t == 0) s_dnrm = sqrt(s_loss[0]);
        __syncthreads();
        double s2 = 0.0;
        for (int i = t; i < KE * KE; i += 256) {
            double v = (double)g_SS[i] / s_dnrm;
            if ((i >> 6) == (i & 63)) v -= 0.125;   // I / sqrt(64)
            s2 += v * v;
        }
        s_loss[t] = s2; __syncthreads();
        for (int off = 128; off >= 1; off >>= 1) { if (t < off) s_loss[t] += s_loss[t + off]; __syncthreads(); }
        if (t == 0) {
            double loss = -(g_cut / g_dt) + sqrt(s_loss[0]);
            out[outIdx] = (float)loss;
        }
    }
}

// ================================================================ launch
extern "C" void kernel_launch(void* const* d_in, const int* in_sizes, int n_in,
                              void* d_out, int out_size) {
    const float* x     = (const float*)d_in[0];
    const int*   ei    = (const int*)  d_in[1];
    const float* MLPW  = (const float*)d_in[2];
    const float* MLPb  = (const float*)d_in[3];
    const float* mlpxW = (const float*)d_in[4];
    const float* mlpxb = (const float*)d_in[5];
    const float* finW  = (const float*)d_in[6];
    const float* finb  = (const float*)d_in[7];
    float* out = (float*)d_out;

    const int* row = ei;
    const int* col = ei + EE;

    int nb = 0;
    cudaOccupancyMaxActiveBlocksPerMultiprocessor(&nb, k_persist, 256, 0);
    if (nb <= 0) nb = 1;
    int smc = 0;
    cudaDeviceGetAttribute(&smc, cudaDevAttrMultiProcessorCount, 0);
    if (smc <= 0) smc = 148;
    unsigned G = (unsigned)(nb * smc);
    if (G > 2048u) G = 2048u;

    void* degp = nullptr;  cudaGetSymbolAddress(&degp, g_deg);
    void* barp = nullptr;  cudaGetSymbolAddress(&barp, g_bar);
    cudaMemsetAsync(degp, 0, NN * sizeof(int));
    cudaMemsetAsync(barp, 0, sizeof(unsigned));

    k_persist<<<G, 256>>>(MLPW, row, col, MLPb, finW, mlpxW, mlpxb, finb, x, out,
                          out_size - 1);
}